// round 9
// baseline (speedup 1.0000x reference)
#include <cuda_runtime.h>

#define MAXN 100000
#define MAXE 1600000

// ---- scratch (static device globals; no allocation) ----
__device__ float  g_u[64];
__device__ float  g_v[64];
__device__ float  g_econst;
__device__ float  g_alpha_q[MAXN];
__device__ float  g_alpha_k[MAXN];
__device__ int    g_cnt[MAXN];
__device__ int    g_off[MAXN];
__device__ int    g_cur[MAXN];
__device__ int    g_bsum[64];
__device__ float2 g_edge[MAXE];          // (ki as bits, ex)
__device__ float  g_kvproj[MAXN * 64];

// u[j] = sum_d wq[d]*W[d][j], v[j] = sum_d wk[d]*W[d][j], econst = b.(wq+wk)+ab
__global__ void prep_kernel(const float* __restrict__ W, const float* __restrict__ b,
                            const float* __restrict__ aw, const float* __restrict__ ab) {
    int j = threadIdx.x;
    float u = 0.f, v = 0.f;
    #pragma unroll 8
    for (int d = 0; d < 64; d++) {
        float w = W[d * 64 + j];
        u += aw[d] * w;
        v += aw[64 + d] * w;
    }
    g_u[j] = u;
    g_v[j] = v;
    if (j == 0) {
        float c = ab[0];
        for (int d = 0; d < 64; d++) c += b[d] * (aw[d] + aw[64 + d]);
        g_econst = c;
    }
}

// one warp per node: alpha_q only (alpha_k folded into kvproj); zero g_cnt
__global__ void alphaq_kernel(const float* __restrict__ q, int Nq) {
    int warp = (blockIdx.x * blockDim.x + threadIdx.x) >> 5;
    int lane = threadIdx.x & 31;
    if (warp >= Nq) return;
    const float* row = q + (size_t)warp * 64;
    float a = row[lane] * g_u[lane] + row[lane + 32] * g_u[lane + 32];
    #pragma unroll
    for (int off = 16; off > 0; off >>= 1) a += __shfl_down_sync(0xffffffffu, a, off);
    if (lane == 0) { g_alpha_q[warp] = a; g_cnt[warp] = 0; }
}

// kv_proj[n][d] = sum_j kv[n][j]*W[d][j] + b[d]; also alpha_k[n] = kv[n].v
#define NPB 32
__global__ __launch_bounds__(256) void kvproj_kernel(const float* __restrict__ kv,
                                                     const float* __restrict__ W,
                                                     const float* __restrict__ b, int Nk) {
    __shared__ float Ws[64 * 65];
    __shared__ float xs[NPB][65];       // padded: lane-varying node read conflict-free
    __shared__ float vs[64];
    int tid = threadIdx.x;

    for (int i = tid; i < 64 * 64; i += 256) {
        int d = i >> 6, j = i & 63;
        Ws[d * 65 + j] = W[i];
    }
    if (tid < 64) vs[tid] = g_v[tid];
    int n0 = blockIdx.x * NPB;
    for (int i = tid; i < NPB * 64; i += 256) {
        int nl = i >> 6, j = i & 63;
        int n = n0 + nl;
        xs[nl][j] = (n < Nk) ? kv[(size_t)n * 64 + j] : 0.f;
    }
    __syncthreads();

    // alpha_k: 32 threads, one node each, conflict-free thanks to padding
    if (tid < NPB) {
        int n = n0 + tid;
        if (n < Nk) {
            float s = 0.f;
            #pragma unroll
            for (int j = 0; j < 64; j++) s += xs[tid][j] * vs[j];
            g_alpha_k[n] = s;
        }
    }

    int d = tid & 63;
    float bd = b[d];
    for (int nl = tid >> 6; nl < NPB; nl += 4) {
        int n = n0 + nl;
        if (n >= Nk) break;
        float acc = bd;
        #pragma unroll
        for (int j = 0; j < 64; j++) acc += xs[nl][j] * Ws[d * 65 + j];
        g_kvproj[(size_t)n * 64 + d] = acc;
    }
}

// degree histogram, 4 edges per thread
__global__ void hist4_kernel(const int* __restrict__ ei, int E4) {
    int t = blockIdx.x * blockDim.x + threadIdx.x;
    if (t >= E4) return;
    int4 q4 = __ldg((const int4*)ei + t);
    atomicAdd(&g_cnt[q4.x], 1);
    atomicAdd(&g_cnt[q4.y], 1);
    atomicAdd(&g_cnt[q4.z], 1);
    atomicAdd(&g_cnt[q4.w], 1);
}
__global__ void hist_kernel(const int* __restrict__ ei, int E) {
    int i = blockIdx.x * blockDim.x + threadIdx.x;
    if (i < E) atomicAdd(&g_cnt[__ldg(&ei[i])], 1);
}

// ---- 2-level exclusive scan over g_cnt[0..Nq) ----
__global__ __launch_bounds__(1024) void scan_a(int Nq) {
    __shared__ int wsum[32];
    int tid = threadIdx.x;
    int base = blockIdx.x * 2048 + tid * 2;
    int c0 = (base     < Nq) ? g_cnt[base]     : 0;
    int c1 = (base + 1 < Nq) ? g_cnt[base + 1] : 0;
    int t = c0 + c1;
    int lane = tid & 31, wid = tid >> 5;
    int v = t;
    #pragma unroll
    for (int o = 1; o < 32; o <<= 1) {
        int n = __shfl_up_sync(0xffffffffu, v, o);
        if (lane >= o) v += n;
    }
    if (lane == 31) wsum[wid] = v;
    __syncthreads();
    if (wid == 0) {
        int s = wsum[lane];
        #pragma unroll
        for (int o = 1; o < 32; o <<= 1) {
            int n = __shfl_up_sync(0xffffffffu, s, o);
            if (lane >= o) s += n;
        }
        wsum[lane] = s;
    }
    __syncthreads();
    int incl = v + (wid > 0 ? wsum[wid - 1] : 0);
    int excl = incl - t;
    if (base     < Nq) g_off[base]     = excl;
    if (base + 1 < Nq) g_off[base + 1] = excl + c0;
    if (tid == 1023) g_bsum[blockIdx.x] = incl;
}

__global__ void scan_b(int nb) {
    if (threadIdx.x == 0) {
        int s = 0;
        for (int i = 0; i < nb; i++) { int c = g_bsum[i]; g_bsum[i] = s; s += c; }
    }
}

__global__ __launch_bounds__(1024) void scan_c(int Nq) {
    int add = g_bsum[blockIdx.x];
    int base = blockIdx.x * 2048 + threadIdx.x * 2;
    #pragma unroll
    for (int k = 0; k < 2; k++) {
        int i = base + k;
        if (i < Nq) {
            int o = g_off[i] + add;
            g_off[i] = o;
            g_cur[i] = o;
        }
    }
}

// per edge: compute ex, place (ki, ex) into qi's bin — 4 edges per thread
__device__ __forceinline__ void scatter_one(int qi, int ki) {
    float e = g_alpha_q[qi] + g_alpha_k[ki] + g_econst;
    e = e > 0.f ? e : 0.2f * e;
    float ex = __expf(e);
    int pos = atomicAdd(&g_cur[qi], 1);
    g_edge[pos] = make_float2(__int_as_float(ki), ex);
}
__global__ void scatter4_kernel(const int* __restrict__ ei, int E) {
    int t = blockIdx.x * blockDim.x + threadIdx.x;
    if (t >= E / 4) return;
    int4 q4 = __ldg((const int4*)ei + t);
    int4 k4 = __ldg((const int4*)(ei + E) + t);
    scatter_one(q4.x, k4.x);
    scatter_one(q4.y, k4.y);
    scatter_one(q4.z, k4.z);
    scatter_one(q4.w, k4.w);
}
__global__ void scatter_kernel(const int* __restrict__ ei, int E) {
    int i = blockIdx.x * blockDim.x + threadIdx.x;
    if (i >= E) return;
    scatter_one(__ldg(&ei[i]), __ldg(&ei[E + i]));
}

// one warp per node, single pass: acc = sum(ex * row), esum folded in, scale at end.
// Half-warp per edge: lanes 0-15 even edges, 16-31 odd edges, float4 row loads.
__global__ __launch_bounds__(256) void agg_kernel(float* __restrict__ out, int Nq) {
    int warp = (blockIdx.x * blockDim.x + threadIdx.x) >> 5;
    int lane = threadIdx.x & 31;
    if (warp >= Nq) return;
    int off = g_off[warp];
    int cnt = g_cnt[warp];
    int half = lane >> 4;
    int hl = lane & 15;

    const float4* kvp = (const float4*)g_kvproj;
    float4 acc = make_float4(0.f, 0.f, 0.f, 0.f);
    float es = 0.f;

    int i = half;
    for (; i + 2 < cnt; i += 4) {
        float2 e0 = __ldg(&g_edge[off + i]);
        float2 e1 = __ldg(&g_edge[off + i + 2]);
        float4 v0 = __ldg(kvp + (size_t)__float_as_int(e0.x) * 16 + hl);
        float4 v1 = __ldg(kvp + (size_t)__float_as_int(e1.x) * 16 + hl);
        es += e0.y + e1.y;
        acc.x += e0.y * v0.x + e1.y * v1.x;
        acc.y += e0.y * v0.y + e1.y * v1.y;
        acc.z += e0.y * v0.z + e1.y * v1.z;
        acc.w += e0.y * v0.w + e1.y * v1.w;
    }
    if (i < cnt) {
        float2 e0 = __ldg(&g_edge[off + i]);
        float4 v0 = __ldg(kvp + (size_t)__float_as_int(e0.x) * 16 + hl);
        es += e0.y;
        acc.x += e0.y * v0.x;
        acc.y += e0.y * v0.y;
        acc.z += e0.y * v0.z;
        acc.w += e0.y * v0.w;
    }

    // combine the two halves
    acc.x += __shfl_xor_sync(0xffffffffu, acc.x, 16);
    acc.y += __shfl_xor_sync(0xffffffffu, acc.y, 16);
    acc.z += __shfl_xor_sync(0xffffffffu, acc.z, 16);
    acc.w += __shfl_xor_sync(0xffffffffu, acc.w, 16);
    es    += __shfl_xor_sync(0xffffffffu, es, 16);

    if (half == 0) {
        float inv = 1.f / (es + 1e-10f);
        float4 o = make_float4(acc.x * inv, acc.y * inv, acc.z * inv, acc.w * inv);
        ((float4*)out)[(size_t)warp * 16 + hl] = o;
    }
}

extern "C" void kernel_launch(void* const* d_in, const int* in_sizes, int n_in,
                              void* d_out, int out_size) {
    const float* q  = (const float*)d_in[0];
    const float* kv = (const float*)d_in[1];
    const int*   ei = (const int*)d_in[2];   // JAX default x64-off: int32
    const float* W  = (const float*)d_in[3];
    const float* b  = (const float*)d_in[4];
    const float* aw = (const float*)d_in[5];
    const float* ab = (const float*)d_in[6];
    float* out = (float*)d_out;

    int Nq = in_sizes[0] / 64;
    int Nk = in_sizes[1] / 64;
    int E  = in_sizes[2] / 2;
    int nb = (Nq + 2047) / 2048;

    prep_kernel<<<1, 64>>>(W, b, aw, ab);
    alphaq_kernel<<<((long long)Nq * 32 + 255) / 256, 256>>>(q, Nq);
    kvproj_kernel<<<(Nk + NPB - 1) / NPB, 256>>>(kv, W, b, Nk);
    if ((E & 3) == 0) {
        hist4_kernel<<<(E / 4 + 255) / 256, 256>>>(ei, E / 4);
    } else {
        hist_kernel<<<(E + 255) / 256, 256>>>(ei, E);
    }
    scan_a<<<nb, 1024>>>(Nq);
    scan_b<<<1, 32>>>(nb);
    scan_c<<<nb, 1024>>>(Nq);
    if ((E & 3) == 0) {
        scatter4_kernel<<<(E / 4 + 255) / 256, 256>>>(ei, E);
    } else {
        scatter_kernel<<<(E + 255) / 256, 256>>>(ei, E);
    }
    agg_kernel<<<((long long)Nq * 32 + 255) / 256, 256>>>(out, Nq);
}

// round 11
// speedup vs baseline: 1.0608x; 1.0608x over previous
#include <cuda_runtime.h>

#define MAXN 100000
#define MAXE 1600000
#define DEG_CAP 64

// ---- scratch (static device globals; no allocation) ----
__device__ float  g_u[64];
__device__ float  g_v[64];
__device__ float  g_econst;
__device__ float  g_alpha_q[MAXN];
__device__ float  g_alpha_k[MAXN];
__device__ int    g_cnt[MAXN];
__device__ int    g_off[MAXN];
__device__ int    g_cur[MAXN];
__device__ int    g_bsum[64];
__device__ float2 g_edge[MAXE];          // (ki as bits, ex)
__device__ float  g_kvproj[MAXN * 64];

// u[j] = sum_d wq[d]*W[d][j], v[j] = sum_d wk[d]*W[d][j], econst = b.(wq+wk)+ab
__global__ void prep_kernel(const float* __restrict__ W, const float* __restrict__ b,
                            const float* __restrict__ aw, const float* __restrict__ ab) {
    int j = threadIdx.x;
    float u = 0.f, v = 0.f;
    #pragma unroll 8
    for (int d = 0; d < 64; d++) {
        float w = W[d * 64 + j];
        u += aw[d] * w;
        v += aw[64 + d] * w;
    }
    g_u[j] = u;
    g_v[j] = v;
    if (j == 0) {
        float c = ab[0];
        for (int d = 0; d < 64; d++) c += b[d] * (aw[d] + aw[64 + d]);
        g_econst = c;
    }
}

// fused: warp per node computes alpha_q; threads < E also do the degree histogram
__global__ void alphaq_hist_kernel(const float* __restrict__ q, const int* __restrict__ ei,
                                   int Nq, int E) {
    int tid = blockIdx.x * blockDim.x + threadIdx.x;
    if (tid < E) atomicAdd(&g_cnt[__ldg(&ei[tid])], 1);
    int warp = tid >> 5;
    int lane = tid & 31;
    if (warp >= Nq) return;
    const float* row = q + (size_t)warp * 64;
    float a = row[lane] * g_u[lane] + row[lane + 32] * g_u[lane + 32];
    #pragma unroll
    for (int off = 16; off > 0; off >>= 1) a += __shfl_down_sync(0xffffffffu, a, off);
    if (lane == 0) g_alpha_q[warp] = a;
}

// kv_proj[n][d] = sum_j kv[n][j]*W[d][j] + b[d]; also alpha_k[n] = kv[n].v
#define NPB 32
__global__ __launch_bounds__(256) void kvproj_kernel(const float* __restrict__ kv,
                                                     const float* __restrict__ W,
                                                     const float* __restrict__ b, int Nk) {
    __shared__ float Ws[64 * 65];
    __shared__ float xs[NPB][65];       // padded: lane-varying node read conflict-free
    __shared__ float vs[64];
    int tid = threadIdx.x;

    for (int i = tid; i < 64 * 64; i += 256) {
        int d = i >> 6, j = i & 63;
        Ws[d * 65 + j] = W[i];
    }
    if (tid < 64) vs[tid] = g_v[tid];
    int n0 = blockIdx.x * NPB;
    for (int i = tid; i < NPB * 64; i += 256) {
        int nl = i >> 6, j = i & 63;
        int n = n0 + nl;
        xs[nl][j] = (n < Nk) ? kv[(size_t)n * 64 + j] : 0.f;
    }
    __syncthreads();

    if (tid < NPB) {
        int n = n0 + tid;
        if (n < Nk) {
            float s = 0.f;
            #pragma unroll
            for (int j = 0; j < 64; j++) s += xs[tid][j] * vs[j];
            g_alpha_k[n] = s;
        }
    }

    int d = tid & 63;
    float bd = b[d];
    for (int nl = tid >> 6; nl < NPB; nl += 4) {
        int n = n0 + nl;
        if (n >= Nk) break;
        float acc = bd;
        #pragma unroll
        for (int j = 0; j < 64; j++) acc += xs[nl][j] * Ws[d * 65 + j];
        g_kvproj[(size_t)n * 64 + d] = acc;
    }
}

// ---- 2-level exclusive scan over g_cnt[0..Nq) ----
__global__ __launch_bounds__(1024) void scan_a(int Nq) {
    __shared__ int wsum[32];
    int tid = threadIdx.x;
    int base = blockIdx.x * 2048 + tid * 2;
    int c0 = (base     < Nq) ? g_cnt[base]     : 0;
    int c1 = (base + 1 < Nq) ? g_cnt[base + 1] : 0;
    int t = c0 + c1;
    int lane = tid & 31, wid = tid >> 5;
    int v = t;
    #pragma unroll
    for (int o = 1; o < 32; o <<= 1) {
        int n = __shfl_up_sync(0xffffffffu, v, o);
        if (lane >= o) v += n;
    }
    if (lane == 31) wsum[wid] = v;
    __syncthreads();
    if (wid == 0) {
        int s = wsum[lane];
        #pragma unroll
        for (int o = 1; o < 32; o <<= 1) {
            int n = __shfl_up_sync(0xffffffffu, s, o);
            if (lane >= o) s += n;
        }
        wsum[lane] = s;
    }
    __syncthreads();
    int incl = v + (wid > 0 ? wsum[wid - 1] : 0);
    int excl = incl - t;
    if (base     < Nq) g_off[base]     = excl;
    if (base + 1 < Nq) g_off[base + 1] = excl + c0;
    if (tid == 1023) g_bsum[blockIdx.x] = incl;
}

// one warp, 2 elems/lane: exclusive scan of nb (<=64) block sums
__global__ void scan_b(int nb) {
    int lane = threadIdx.x;
    int i0 = 2 * lane, i1 = 2 * lane + 1;
    int a = (i0 < nb) ? g_bsum[i0] : 0;
    int c = (i1 < nb) ? g_bsum[i1] : 0;
    int t = a + c;
    int v = t;
    #pragma unroll
    for (int o = 1; o < 32; o <<= 1) {
        int n = __shfl_up_sync(0xffffffffu, v, o);
        if (lane >= o) v += n;
    }
    int excl = v - t;
    if (i0 < nb) g_bsum[i0] = excl;
    if (i1 < nb) g_bsum[i1] = excl + a;
}

__global__ __launch_bounds__(1024) void scan_c(int Nq) {
    int add = g_bsum[blockIdx.x];
    int base = blockIdx.x * 2048 + threadIdx.x * 2;
    #pragma unroll
    for (int k = 0; k < 2; k++) {
        int i = base + k;
        if (i < Nq) {
            int o = g_off[i] + add;
            g_off[i] = o;
            g_cur[i] = o;
        }
    }
}

// per edge: compute ex, place (ki, ex) into qi's bin
__global__ void scatter_kernel(const int* __restrict__ ei, int E) {
    int i = blockIdx.x * blockDim.x + threadIdx.x;
    if (i >= E) return;
    int qi = __ldg(&ei[i]);
    int ki = __ldg(&ei[E + i]);
    float e = g_alpha_q[qi] + g_alpha_k[ki] + g_econst;
    e = e > 0.f ? e : 0.2f * e;
    float ex = __expf(e);
    int pos = atomicAdd(&g_cur[qi], 1);
    g_edge[pos] = make_float2(__int_as_float(ki), ex);
}

// one warp per node, single pass. Edge list staged in smem (degree <= DEG_CAP),
// then the gather loop has a one-level latency chain with MLP 8.
__global__ __launch_bounds__(256) void agg_kernel(float* __restrict__ out, int Nq) {
    __shared__ float2 eb[8][DEG_CAP];
    int wline = threadIdx.x >> 5;
    int warp = (blockIdx.x * blockDim.x + threadIdx.x) >> 5;
    int lane = threadIdx.x & 31;
    if (warp >= Nq) return;
    int off = g_off[warp];
    int cnt = g_cnt[warp];

    float a0 = 0.f, a1 = 0.f;
    float es = 0.f;

    if (cnt <= DEG_CAP) {
        // stage edges in smem; fold esum into the same sweep
        if (lane < cnt) {
            float2 e = __ldg(&g_edge[off + lane]);
            eb[wline][lane] = e;
            es += e.y;
        }
        if (lane + 32 < cnt) {
            float2 e = __ldg(&g_edge[off + lane + 32]);
            eb[wline][lane + 32] = e;
            es += e.y;
        }
        __syncwarp();
        #pragma unroll
        for (int o = 16; o > 0; o >>= 1) es += __shfl_xor_sync(0xffffffffu, es, o);

        int i = 0;
        for (; i + 4 <= cnt; i += 4) {
            float2 e0 = eb[wline][i];
            float2 e1 = eb[wline][i + 1];
            float2 e2 = eb[wline][i + 2];
            float2 e3 = eb[wline][i + 3];
            const float* r0 = g_kvproj + (size_t)__float_as_int(e0.x) * 64;
            const float* r1 = g_kvproj + (size_t)__float_as_int(e1.x) * 64;
            const float* r2 = g_kvproj + (size_t)__float_as_int(e2.x) * 64;
            const float* r3 = g_kvproj + (size_t)__float_as_int(e3.x) * 64;
            a0 += e0.y * __ldg(&r0[lane])      + e1.y * __ldg(&r1[lane])
                + e2.y * __ldg(&r2[lane])      + e3.y * __ldg(&r3[lane]);
            a1 += e0.y * __ldg(&r0[lane + 32]) + e1.y * __ldg(&r1[lane + 32])
                + e2.y * __ldg(&r2[lane + 32]) + e3.y * __ldg(&r3[lane + 32]);
        }
        for (; i < cnt; i++) {
            float2 e0 = eb[wline][i];
            const float* r0 = g_kvproj + (size_t)__float_as_int(e0.x) * 64;
            a0 += e0.y * __ldg(&r0[lane]);
            a1 += e0.y * __ldg(&r0[lane + 32]);
        }
    } else {
        // rare fallback: two-pass streaming from global
        for (int i = lane; i < cnt; i += 32) es += __ldg(&g_edge[off + i]).y;
        #pragma unroll
        for (int o = 16; o > 0; o >>= 1) es += __shfl_xor_sync(0xffffffffu, es, o);
        for (int i = 0; i < cnt; i++) {
            float2 e0 = __ldg(&g_edge[off + i]);
            const float* r0 = g_kvproj + (size_t)__float_as_int(e0.x) * 64;
            a0 += e0.y * __ldg(&r0[lane]);
            a1 += e0.y * __ldg(&r0[lane + 32]);
        }
    }

    float inv = 1.f / (es + 1e-10f);
    out[(size_t)warp * 64 + lane]      = a0 * inv;
    out[(size_t)warp * 64 + lane + 32] = a1 * inv;
}

extern "C" void kernel_launch(void* const* d_in, const int* in_sizes, int n_in,
                              void* d_out, int out_size) {
    const float* q  = (const float*)d_in[0];
    const float* kv = (const float*)d_in[1];
    const int*   ei = (const int*)d_in[2];   // JAX default x64-off: int32
    const float* W  = (const float*)d_in[3];
    const float* b  = (const float*)d_in[4];
    const float* aw = (const float*)d_in[5];
    const float* ab = (const float*)d_in[6];
    float* out = (float*)d_out;

    int Nq = in_sizes[0] / 64;
    int Nk = in_sizes[1] / 64;
    int E  = in_sizes[2] / 2;
    int nb = (Nq + 2047) / 2048;

    void* cnt_ptr = nullptr;
    cudaGetSymbolAddress(&cnt_ptr, g_cnt);
    cudaMemsetAsync(cnt_ptr, 0, (size_t)Nq * sizeof(int));

    prep_kernel<<<1, 64>>>(W, b, aw, ab);
    long long tfused = (long long)Nq * 32;
    if (tfused < E) tfused = E;
    alphaq_hist_kernel<<<(tfused + 255) / 256, 256>>>(q, ei, Nq, E);
    kvproj_kernel<<<(Nk + NPB - 1) / NPB, 256>>>(kv, W, b, Nk);
    scan_a<<<nb, 1024>>>(Nq);
    scan_b<<<1, 32>>>(nb);
    scan_c<<<nb, 1024>>>(Nq);
    scatter_kernel<<<(E + 255) / 256, 256>>>(ei, E);
    agg_kernel<<<((long long)Nq * 32 + 255) / 256, 256>>>(out, Nq);
}